// round 8
// baseline (speedup 1.0000x reference)
#include <cuda_runtime.h>

#define N_NODES 163842
#define N_EDGES 983040
#define SCAN_B  1024
#define SCAN_NB ((N_NODES + SCAN_B - 1) / SCAN_B)   // 161

// ---------------- scratch (device globals; no allocation allowed) ----------------
__device__ float d_agg[(size_t)N_NODES * 192];   // gathered mean_k(gauss_k * x[src]) [N, 3*Cin]
__device__ float d_h0[(size_t)N_NODES * 64];
__device__ float d_h1[(size_t)N_NODES * 64];
__device__ float4 d_g4[3][N_EDGES];              // per-layer edge gaussians (CSR order)
__device__ float2 d_csr_ea[N_EDGES];
__device__ int   d_csr_src[N_EDGES];
__device__ int   d_src[N_EDGES];
__device__ int   d_dst[N_EDGES];
__device__ int   d_cnt[N_NODES];
__device__ int   d_incl[N_NODES];
__device__ int   d_rowptr[N_NODES + 1];
__device__ int   d_cursor[N_NODES];
__device__ int   d_bsum[SCAN_NB];
__device__ int   d_is64;

// ---------------- edge index handling ----------------
__global__ void detect_kernel(const unsigned* ei) {
    if (threadIdx.x == 0) {
        int ok = 1;
        for (int i = 1; i < 64; i += 2)
            if (ei[i] != 0u) ok = 0;
        d_is64 = ok;
    }
}

__global__ void zero_cnt() {
    int i = blockIdx.x * blockDim.x + threadIdx.x;
    if (i < N_NODES) d_cnt[i] = 0;
}

__global__ void convert_hist(const void* eiv) {
    int e = blockIdx.x * blockDim.x + threadIdx.x;
    if (e >= N_EDGES) return;
    int s, d;
    if (d_is64) {
        const long long* ei = (const long long*)eiv;
        s = (int)ei[e]; d = (int)ei[N_EDGES + e];
    } else {
        const int* ei = (const int*)eiv;
        s = ei[e]; d = ei[N_EDGES + e];
    }
    d_src[e] = s;
    d_dst[e] = d;
    atomicAdd(&d_cnt[d], 1);
}

// ---------------- CSR build ----------------
__global__ void scan1() {
    __shared__ int s[2][SCAN_B];
    int t = threadIdx.x;
    int i = blockIdx.x * SCAN_B + t;
    int v = (i < N_NODES) ? d_cnt[i] : 0;
    s[0][t] = v;
    int cur = 0;
    for (int off = 1; off < SCAN_B; off <<= 1) {
        __syncthreads();
        int nv = s[cur][t] + (t >= off ? s[cur][t - off] : 0);
        s[cur ^ 1][t] = nv;
        cur ^= 1;
    }
    __syncthreads();
    if (i < N_NODES) d_incl[i] = s[cur][t];
    if (t == SCAN_B - 1) d_bsum[blockIdx.x] = s[cur][t];
}

__global__ void scan2() {   // parallel scan of the 161 block sums
    __shared__ int s[2][256];
    int t = threadIdx.x;
    int v = (t < SCAN_NB) ? d_bsum[t] : 0;
    s[0][t] = v;
    int cur = 0;
    for (int off = 1; off < 256; off <<= 1) {
        __syncthreads();
        int nv = s[cur][t] + (t >= off ? s[cur][t - off] : 0);
        s[cur ^ 1][t] = nv;
        cur ^= 1;
    }
    __syncthreads();
    if (t < SCAN_NB) d_bsum[t] = s[cur][t] - v;        // exclusive
    if (t == 255) d_rowptr[N_NODES] = s[cur][t];
}

__global__ void scan3() {
    int i = blockIdx.x * blockDim.x + threadIdx.x;
    if (i >= N_NODES) return;
    int excl = d_incl[i] - d_cnt[i] + d_bsum[i / SCAN_B];
    d_rowptr[i] = excl;
    d_cursor[i] = excl;
}

__global__ void fill_kernel(const float* __restrict__ ea) {
    int e = blockIdx.x * blockDim.x + threadIdx.x;
    if (e >= N_EDGES) return;
    int p = atomicAdd(&d_cursor[d_dst[e]], 1);
    d_csr_src[p] = d_src[e];
    d_csr_ea[p] = ((const float2*)ea)[e];
}

// ---------------- Gaussian weights, all 3 layers in one pass ----------------
__global__ void gauss_all(const float* __restrict__ mu0, const float* __restrict__ sg0,
                          const float* __restrict__ mu1, const float* __restrict__ sg1,
                          const float* __restrict__ mu2, const float* __restrict__ sg2) {
    int i = blockIdx.x * blockDim.x + threadIdx.x;
    if (i >= N_EDGES) return;
    float2 pc = d_csr_ea[i];
    const float* mus[3] = {mu0, mu1, mu2};
    const float* sgs[3] = {sg0, sg1, sg2};
#pragma unroll
    for (int l = 0; l < 3; l++) {
        float g[3];
#pragma unroll
        for (int k = 0; k < 3; k++) {
            float dd0 = pc.x - mus[l][2 * k];
            float dd1 = pc.y - mus[l][2 * k + 1];
            float s0 = sgs[l][2 * k], s1 = sgs[l][2 * k + 1];
            float q = dd0 * dd0 / (1e-15f + s0 * s0) + dd1 * dd1 / (1e-15f + s1 * s1);
            g[k] = __expf(-0.5f * q);
        }
        d_g4[l][i] = make_float4(g[0], g[1], g[2], 0.f);
    }
}

// ---------------- gather x first: agg[n, k*CIN+c] = mean_e gauss_k(e) * x[src(e), c]
template <int CIN, int CPL>
__global__ void gatherx(const float* __restrict__ x,
                        const float4* __restrict__ g4,
                        float* __restrict__ agg) {
    int warp = (blockIdx.x * blockDim.x + threadIdx.x) >> 5;
    int lane = threadIdx.x & 31;
    if (warp >= N_NODES) return;
    int beg = d_rowptr[warp], end = d_rowptr[warp + 1];
    float acc[3][CPL];
#pragma unroll
    for (int k = 0; k < 3; k++)
#pragma unroll
        for (int r = 0; r < CPL; r++) acc[k][r] = 0.f;

    for (int i = beg; i < end; i++) {
        int s = d_csr_src[i];
        float4 gg = g4[i];
#pragma unroll
        for (int r = 0; r < CPL; r++) {
            int c = lane + 32 * r;
            float xv = (c < CIN) ? x[(size_t)s * CIN + c] : 0.f;
            acc[0][r] += gg.x * xv;
            acc[1][r] += gg.y * xv;
            acc[2][r] += gg.z * xv;
        }
    }
    float inv = 1.f / fmaxf((float)(end - beg), 1.f);
#pragma unroll
    for (int k = 0; k < 3; k++)
#pragma unroll
        for (int r = 0; r < CPL; r++) {
            int c = lane + 32 * r;
            if (c < CIN)
                agg[(size_t)warp * (3 * CIN) + k * CIN + c] = acc[k][r] * inv;
        }
}

// ---------------- GEMM: out = relu([agg | h] @ [Wmsg ; root] + bias) --------------
// Wmsg[k*CIN+c, o] = g[c, k*COUT+o].  Block (16,16), BN = 16*TN nodes.
// FINAL: fuse 64->2 FC + log_softmax in epilogue (COUT=64, VW=4 only).
template <int CIN, int CC, int COUT, int VW, int TN, bool FINAL>
__global__ void __launch_bounds__(256) gemm2(const float* __restrict__ agg,
                                             const float* __restrict__ h,
                                             const float* __restrict__ g,
                                             const float* __restrict__ root,
                                             const float* __restrict__ bias,
                                             const float* __restrict__ fcw,
                                             const float* __restrict__ fcb,
                                             float* __restrict__ out) {
    constexpr int K3 = 3 * CIN;
    constexpr int K4 = 4 * CIN;
    constexpr int BN = 16 * TN;
    __shared__ __align__(16) float gs[CC * COUT];
    __shared__ float xs[BN * CC];
    const int tx = threadIdx.x, ty = threadIdx.y;
    const int tid = ty * 16 + tx;
    const int n0 = blockIdx.x * BN;
    const int nb = ty * TN;

    float acc[TN][VW];
#pragma unroll
    for (int j = 0; j < TN; j++)
#pragma unroll
        for (int v = 0; v < VW; v++) acc[j][v] = 0.f;

    for (int c0 = 0; c0 < K4; c0 += CC) {
        __syncthreads();
        for (int i = tid; i < CC * COUT; i += 256) {
            int r = c0 + i / COUT, col = i % COUT;
            float v;
            if (r < K3) {
                int k = r / CIN, c = r - k * CIN;
                v = g[c * (3 * COUT) + k * COUT + col];
            } else {
                v = root[(r - K3) * COUT + col];
            }
            gs[i] = v;
        }
        for (int i = tid; i < BN * CC; i += 256) {
            int nn = i / CC, cc = i - nn * CC;
            int n = n0 + nn, r = c0 + cc;
            float v = 0.f;
            if (n < N_NODES)
                v = (r < K3) ? agg[(size_t)n * K3 + r] : h[(size_t)n * CIN + (r - K3)];
            xs[i] = v;
        }
        __syncthreads();
#pragma unroll
        for (int cc = 0; cc < CC; cc++) {
            float wv[VW];
            if (VW == 4) {
                float4 t = *(const float4*)&gs[cc * COUT + tx * 4];
                wv[0] = t.x; wv[1] = t.y; wv[2] = t.z; wv[3] = t.w;
            } else {
                float2 t = *(const float2*)&gs[cc * COUT + tx * 2];
                wv[0] = t.x; wv[1] = t.y;
            }
#pragma unroll
            for (int j = 0; j < TN; j++) {
                float xc = xs[(nb + j) * CC + cc];
#pragma unroll
                for (int v = 0; v < VW; v++) acc[j][v] += xc * wv[v];
            }
        }
    }

#pragma unroll
    for (int j = 0; j < TN; j++) {
        int n = n0 + nb + j;
        float hv[VW];
#pragma unroll
        for (int v = 0; v < VW; v++)
            hv[v] = fmaxf(acc[j][v] + bias[tx * VW + v], 0.f);
        if (!FINAL) {
            if (n < N_NODES) {
                if (VW == 4)
                    *(float4*)&out[(size_t)n * COUT + tx * 4] =
                        make_float4(hv[0], hv[1], hv[2], hv[3]);
                else
                    *(float2*)&out[(size_t)n * COUT + tx * 2] = make_float2(hv[0], hv[1]);
            }
        } else {
            float p0 = 0.f, p1 = 0.f;
#pragma unroll
            for (int v = 0; v < VW; v++) {
                int o = tx * VW + v;
                p0 += hv[v] * fcw[2 * o];
                p1 += hv[v] * fcw[2 * o + 1];
            }
#pragma unroll
            for (int off = 8; off > 0; off >>= 1) {   // reduce across the 16 tx lanes
                p0 += __shfl_xor_sync(0xffffffffu, p0, off);
                p1 += __shfl_xor_sync(0xffffffffu, p1, off);
            }
            if (tx == 0 && n < N_NODES) {
                float l0 = p0 + fcb[0], l1 = p1 + fcb[1];
                float mx = fmaxf(l0, l1);
                float lse = mx + logf(expf(l0 - mx) + expf(l1 - mx));
                out[(size_t)n * 2]     = l0 - lse;
                out[(size_t)n * 2 + 1] = l1 - lse;
            }
        }
    }
}

// ---------------- launch ----------------------------------------------------------
extern "C" void kernel_launch(void* const* d_in, const int* in_sizes, int n_in,
                              void* d_out, int out_size) {
    const float* x   = (const float*)d_in[0];
    const void*  ei  = d_in[1];
    const float* ea  = (const float*)d_in[2];
    const float* g[3]  = {(const float*)d_in[3],  (const float*)d_in[8],  (const float*)d_in[13]};
    const float* mu[3] = {(const float*)d_in[4],  (const float*)d_in[9],  (const float*)d_in[14]};
    const float* sg[3] = {(const float*)d_in[5],  (const float*)d_in[10], (const float*)d_in[15]};
    const float* rt[3] = {(const float*)d_in[6],  (const float*)d_in[11], (const float*)d_in[16]};
    const float* bi[3] = {(const float*)d_in[7],  (const float*)d_in[12], (const float*)d_in[17]};
    const float* fcw = (const float*)d_in[18];
    const float* fcb = (const float*)d_in[19];
    float* out = (float*)d_out;

    float *agg, *h0, *h1;
    float4* g4;
    cudaGetSymbolAddress((void**)&agg, d_agg);
    cudaGetSymbolAddress((void**)&h0,  d_h0);
    cudaGetSymbolAddress((void**)&h1,  d_h1);
    cudaGetSymbolAddress((void**)&g4,  d_g4);

    const int EB = (N_EDGES + 255) / 256;
    const int NB = (N_NODES + 255) / 256;
    const int GW = (N_NODES * 32 + 255) / 256;     // warp-per-node grids
    const int GB = (N_NODES + 127) / 128;          // gemm grids (BN=128)

    // ---- CSR build (shared by all 3 layers) ----
    detect_kernel<<<1, 32>>>((const unsigned*)ei);
    zero_cnt<<<NB, 256>>>();
    convert_hist<<<EB, 256>>>(ei);
    scan1<<<SCAN_NB, SCAN_B>>>();
    scan2<<<1, 256>>>();
    scan3<<<NB, 256>>>();
    fill_kernel<<<EB, 256>>>(ea);
    gauss_all<<<EB, 256>>>(mu[0], sg[0], mu[1], sg[1], mu[2], sg[2]);

    // ---- layer 0: 22 -> 32 ----
    gatherx<22, 1><<<GW, 256>>>(x, g4, agg);
    gemm2<22, 22, 32, 2, 8, false><<<GB, dim3(16, 16)>>>(agg, x, g[0], rt[0], bi[0], fcw, fcb, h0);

    // ---- layer 1: 32 -> 64 ----
    gatherx<32, 1><<<GW, 256>>>(h0, g4 + N_EDGES, agg);
    gemm2<32, 32, 64, 4, 8, false><<<GB, dim3(16, 16)>>>(agg, h0, g[1], rt[1], bi[1], fcw, fcb, h1);

    // ---- layer 2: 64 -> 64 (fused FC + log_softmax) ----
    gatherx<64, 2><<<GW, 256>>>(h1, g4 + 2 * (size_t)N_EDGES, agg);
    gemm2<64, 32, 64, 4, 8, true><<<GB, dim3(16, 16)>>>(agg, h1, g[2], rt[2], bi[2], fcw, fcb, out);
}

// round 9
// speedup vs baseline: 1.3575x; 1.3575x over previous
#include <cuda_runtime.h>

#define N_NODES 163842
#define N_EDGES 983040
#define SCAN_B  1024
#define SCAN_NB ((N_NODES + SCAN_B - 1) / SCAN_B)   // 161

// ---------------- scratch (device globals; no allocation allowed) ----------------
__device__ float d_agg[(size_t)N_NODES * 256];   // [N, 4*Cin]: [3*Cin gathered | Cin self]
__device__ float d_h0[(size_t)N_NODES * 64];
__device__ float d_h1[(size_t)N_NODES * 64];
__device__ float d_W[3][256 * 64];               // packed [4*Cin, Cout] per layer
__device__ float4 d_g4[3][N_EDGES];              // per-layer edge gaussians (CSR order)
__device__ float2 d_csr_ea[N_EDGES];
__device__ int   d_csr_src[N_EDGES];
__device__ int   d_src[N_EDGES];
__device__ int   d_dst[N_EDGES];
__device__ int   d_cnt[N_NODES];
__device__ int   d_incl[N_NODES];
__device__ int   d_rowptr[N_NODES + 1];
__device__ int   d_cursor[N_NODES];
__device__ int   d_bsum[SCAN_NB];
__device__ int   d_is64;

// ---------------- edge index handling ----------------
__global__ void detect_kernel(const unsigned* ei) {
    if (threadIdx.x == 0) {
        int ok = 1;
        for (int i = 1; i < 64; i += 2)
            if (ei[i] != 0u) ok = 0;
        d_is64 = ok;
    }
}

__global__ void zero_cnt() {
    int i = blockIdx.x * blockDim.x + threadIdx.x;
    if (i < N_NODES) d_cnt[i] = 0;
}

__global__ void convert_hist(const void* eiv) {
    int e = blockIdx.x * blockDim.x + threadIdx.x;
    if (e >= N_EDGES) return;
    int s, d;
    if (d_is64) {
        const long long* ei = (const long long*)eiv;
        s = (int)ei[e]; d = (int)ei[N_EDGES + e];
    } else {
        const int* ei = (const int*)eiv;
        s = ei[e]; d = ei[N_EDGES + e];
    }
    d_src[e] = s;
    d_dst[e] = d;
    atomicAdd(&d_cnt[d], 1);
}

// ---------------- CSR build ----------------
__global__ void scan1() {
    __shared__ int s[2][SCAN_B];
    int t = threadIdx.x;
    int i = blockIdx.x * SCAN_B + t;
    int v = (i < N_NODES) ? d_cnt[i] : 0;
    s[0][t] = v;
    int cur = 0;
    for (int off = 1; off < SCAN_B; off <<= 1) {
        __syncthreads();
        int nv = s[cur][t] + (t >= off ? s[cur][t - off] : 0);
        s[cur ^ 1][t] = nv;
        cur ^= 1;
    }
    __syncthreads();
    if (i < N_NODES) d_incl[i] = s[cur][t];
    if (t == SCAN_B - 1) d_bsum[blockIdx.x] = s[cur][t];
}

__global__ void scan2() {
    __shared__ int s[2][256];
    int t = threadIdx.x;
    int v = (t < SCAN_NB) ? d_bsum[t] : 0;
    s[0][t] = v;
    int cur = 0;
    for (int off = 1; off < 256; off <<= 1) {
        __syncthreads();
        int nv = s[cur][t] + (t >= off ? s[cur][t - off] : 0);
        s[cur ^ 1][t] = nv;
        cur ^= 1;
    }
    __syncthreads();
    if (t < SCAN_NB) d_bsum[t] = s[cur][t] - v;        // exclusive
    if (t == 255) d_rowptr[N_NODES] = s[cur][t];
}

__global__ void scan3() {
    int i = blockIdx.x * blockDim.x + threadIdx.x;
    if (i >= N_NODES) return;
    int excl = d_incl[i] - d_cnt[i] + d_bsum[i / SCAN_B];
    d_rowptr[i] = excl;
    d_cursor[i] = excl;
}

__global__ void fill_kernel(const float* __restrict__ ea) {
    int e = blockIdx.x * blockDim.x + threadIdx.x;
    if (e >= N_EDGES) return;
    int p = atomicAdd(&d_cursor[d_dst[e]], 1);
    d_csr_src[p] = d_src[e];
    d_csr_ea[p] = ((const float2*)ea)[e];
}

// ---------------- Gaussian weights, all 3 layers in one pass ----------------
__global__ void gauss_all(const float* __restrict__ mu0, const float* __restrict__ sg0,
                          const float* __restrict__ mu1, const float* __restrict__ sg1,
                          const float* __restrict__ mu2, const float* __restrict__ sg2) {
    int i = blockIdx.x * blockDim.x + threadIdx.x;
    if (i >= N_EDGES) return;
    float2 pc = d_csr_ea[i];
    const float* mus[3] = {mu0, mu1, mu2};
    const float* sgs[3] = {sg0, sg1, sg2};
#pragma unroll
    for (int l = 0; l < 3; l++) {
        float g[3];
#pragma unroll
        for (int k = 0; k < 3; k++) {
            float dd0 = pc.x - mus[l][2 * k];
            float dd1 = pc.y - mus[l][2 * k + 1];
            float s0 = sgs[l][2 * k], s1 = sgs[l][2 * k + 1];
            float q = dd0 * dd0 / (1e-15f + s0 * s0) + dd1 * dd1 / (1e-15f + s1 * s1);
            g[k] = __expf(-0.5f * q);
        }
        d_g4[l][i] = make_float4(g[0], g[1], g[2], 0.f);
    }
}

// ---------------- pack weights: W[r, o], r<3Cin -> g (k=r/Cin,c=r%Cin), else root -
template <int CIN, int COUT>
__global__ void pack_w(const float* __restrict__ g,
                       const float* __restrict__ root,
                       float* __restrict__ W) {
    constexpr int K3 = 3 * CIN, K4 = 4 * CIN;
    int i = blockIdx.x * blockDim.x + threadIdx.x;
    if (i >= K4 * COUT) return;
    int r = i / COUT, col = i - r * COUT;
    float v;
    if (r < K3) {
        int k = r / CIN, c = r - k * CIN;
        v = g[c * (3 * COUT) + k * COUT + col];
    } else {
        v = root[(r - K3) * COUT + col];
    }
    W[i] = v;
}

// ---------------- gather: agg[n, k*Cin+c] = mean_e g_k(e) x[src,c]; agg[n,3Cin+c]=x[n,c]
template <int CIN, int CPL>
__global__ void gatherx(const float* __restrict__ x,
                        const float4* __restrict__ g4,
                        float* __restrict__ agg) {
    constexpr int K4 = 4 * CIN;
    int warp = (blockIdx.x * blockDim.x + threadIdx.x) >> 5;
    int lane = threadIdx.x & 31;
    if (warp >= N_NODES) return;
    int beg = d_rowptr[warp], end = d_rowptr[warp + 1];
    float acc[3][CPL];
#pragma unroll
    for (int k = 0; k < 3; k++)
#pragma unroll
        for (int r = 0; r < CPL; r++) acc[k][r] = 0.f;

    for (int i = beg; i < end; i++) {
        int s = d_csr_src[i];
        float4 gg = g4[i];
#pragma unroll
        for (int r = 0; r < CPL; r++) {
            int c = lane + 32 * r;
            float xv = (c < CIN) ? x[(size_t)s * CIN + c] : 0.f;
            acc[0][r] += gg.x * xv;
            acc[1][r] += gg.y * xv;
            acc[2][r] += gg.z * xv;
        }
    }
    float inv = 1.f / fmaxf((float)(end - beg), 1.f);
#pragma unroll
    for (int r = 0; r < CPL; r++) {
        int c = lane + 32 * r;
        if (c < CIN) {
            size_t base = (size_t)warp * K4;
#pragma unroll
            for (int k = 0; k < 3; k++)
                agg[base + k * CIN + c] = acc[k][r] * inv;
            agg[base + 3 * CIN + c] = x[(size_t)warp * CIN + c];   // self row
        }
    }
}

// ---------------- GEMM: out = relu(agg[N,K4] @ W[K4,COUT] + bias) -----------------
// Block (16,16), BN = 16*TN nodes; proven c4/q float4 inner loop (0.09 LDS/FMA).
// FINAL: fuse 64->2 FC + log_softmax in epilogue.
template <int CIN, int COUT, int CC, int VW, int TN, bool FINAL>
__global__ void __launch_bounds__(256) gemm2(const float* __restrict__ agg,
                                             const float* __restrict__ W,
                                             const float* __restrict__ bias,
                                             const float* __restrict__ fcw,
                                             const float* __restrict__ fcb,
                                             float* __restrict__ out) {
    constexpr int K4 = 4 * CIN;
    constexpr int BN = 16 * TN;
    __shared__ __align__(16) float gs[CC * COUT];
    __shared__ __align__(16) float xs[BN * CC];
    const int tx = threadIdx.x, ty = threadIdx.y;
    const int tid = ty * 16 + tx;
    const int n0 = blockIdx.x * BN;
    const int nb = ty * TN;

    float acc[TN][VW];
#pragma unroll
    for (int j = 0; j < TN; j++)
#pragma unroll
        for (int v = 0; v < VW; v++) acc[j][v] = 0.f;

    for (int c0 = 0; c0 < K4; c0 += CC) {
        __syncthreads();
        for (int i = tid; i < CC * COUT / 4; i += 256)
            ((float4*)gs)[i] = ((const float4*)(W + c0 * COUT))[i];
        for (int i = tid; i < BN * CC / 4; i += 256) {
            int n = (i * 4) / CC, c = (i * 4) - n * CC;
            int gn = n0 + n;
            float4 v = make_float4(0.f, 0.f, 0.f, 0.f);
            if (gn < N_NODES)
                v = *(const float4*)&agg[(size_t)gn * K4 + c0 + c];
            ((float4*)xs)[i] = v;
        }
        __syncthreads();
#pragma unroll
        for (int c4 = 0; c4 < CC; c4 += 4) {
            float4 xv[TN];
#pragma unroll
            for (int j = 0; j < TN; j++)
                xv[j] = *(const float4*)&xs[(nb + j) * CC + c4];
#pragma unroll
            for (int q = 0; q < 4; q++) {
                float wv[VW];
                if (VW == 4) {
                    float4 t = *(const float4*)&gs[(c4 + q) * COUT + tx * 4];
                    wv[0] = t.x; wv[1] = t.y; wv[2] = t.z; wv[3] = t.w;
                } else {
                    float2 t = *(const float2*)&gs[(c4 + q) * COUT + tx * 2];
                    wv[0] = t.x; wv[1] = t.y;
                }
#pragma unroll
                for (int j = 0; j < TN; j++) {
                    float xc = ((const float*)&xv[j])[q];
#pragma unroll
                    for (int v = 0; v < VW; v++) acc[j][v] += xc * wv[v];
                }
            }
        }
    }

#pragma unroll
    for (int j = 0; j < TN; j++) {
        int n = n0 + nb + j;
        float hv[VW];
#pragma unroll
        for (int v = 0; v < VW; v++)
            hv[v] = fmaxf(acc[j][v] + bias[tx * VW + v], 0.f);
        if (!FINAL) {
            if (n < N_NODES) {
                if (VW == 4)
                    *(float4*)&out[(size_t)n * COUT + tx * 4] =
                        make_float4(hv[0], hv[1], hv[2], hv[3]);
                else
                    *(float2*)&out[(size_t)n * COUT + tx * 2] = make_float2(hv[0], hv[1]);
            }
        } else {
            float p0 = 0.f, p1 = 0.f;
#pragma unroll
            for (int v = 0; v < VW; v++) {
                int o = tx * VW + v;
                p0 += hv[v] * fcw[2 * o];
                p1 += hv[v] * fcw[2 * o + 1];
            }
#pragma unroll
            for (int off = 8; off > 0; off >>= 1) {   // reduce across 16 tx lanes
                p0 += __shfl_xor_sync(0xffffffffu, p0, off);
                p1 += __shfl_xor_sync(0xffffffffu, p1, off);
            }
            if (tx == 0 && n < N_NODES) {
                float l0 = p0 + fcb[0], l1 = p1 + fcb[1];
                float mx = fmaxf(l0, l1);
                float lse = mx + logf(expf(l0 - mx) + expf(l1 - mx));
                out[(size_t)n * 2]     = l0 - lse;
                out[(size_t)n * 2 + 1] = l1 - lse;
            }
        }
    }
}

// ---------------- launch ----------------------------------------------------------
extern "C" void kernel_launch(void* const* d_in, const int* in_sizes, int n_in,
                              void* d_out, int out_size) {
    const float* x   = (const float*)d_in[0];
    const void*  ei  = d_in[1];
    const float* ea  = (const float*)d_in[2];
    const float* g[3]  = {(const float*)d_in[3],  (const float*)d_in[8],  (const float*)d_in[13]};
    const float* mu[3] = {(const float*)d_in[4],  (const float*)d_in[9],  (const float*)d_in[14]};
    const float* sg[3] = {(const float*)d_in[5],  (const float*)d_in[10], (const float*)d_in[15]};
    const float* rt[3] = {(const float*)d_in[6],  (const float*)d_in[11], (const float*)d_in[16]};
    const float* bi[3] = {(const float*)d_in[7],  (const float*)d_in[12], (const float*)d_in[17]};
    const float* fcw = (const float*)d_in[18];
    const float* fcb = (const float*)d_in[19];
    float* out = (float*)d_out;

    float *agg, *h0, *h1, *W;
    float4* g4;
    cudaGetSymbolAddress((void**)&agg, d_agg);
    cudaGetSymbolAddress((void**)&h0,  d_h0);
    cudaGetSymbolAddress((void**)&h1,  d_h1);
    cudaGetSymbolAddress((void**)&W,   d_W);
    cudaGetSymbolAddress((void**)&g4,  d_g4);
    float* W0 = W;
    float* W1 = W + 256 * 64;
    float* W2 = W + 2 * 256 * 64;

    const int EB = (N_EDGES + 255) / 256;
    const int NB = (N_NODES + 255) / 256;
    const int GW = (N_NODES * 32 + 255) / 256;     // warp-per-node grids
    const int GB = (N_NODES + 127) / 128;          // gemm grids (BN=128)

    // ---- CSR build + weights pack (shared prep) ----
    detect_kernel<<<1, 32>>>((const unsigned*)ei);
    zero_cnt<<<NB, 256>>>();
    convert_hist<<<EB, 256>>>(ei);
    scan1<<<SCAN_NB, SCAN_B>>>();
    scan2<<<1, 256>>>();
    scan3<<<NB, 256>>>();
    fill_kernel<<<EB, 256>>>(ea);
    gauss_all<<<EB, 256>>>(mu[0], sg[0], mu[1], sg[1], mu[2], sg[2]);
    pack_w<22, 32><<<(88 * 32 + 255) / 256, 256>>>(g[0], rt[0], W0);
    pack_w<32, 64><<<(128 * 64 + 255) / 256, 256>>>(g[1], rt[1], W1);
    pack_w<64, 64><<<(256 * 64 + 255) / 256, 256>>>(g[2], rt[2], W2);

    // ---- layer 0: 22 -> 32 ----
    gatherx<22, 1><<<GW, 256>>>(x, g4, agg);
    gemm2<22, 32, 44, 2, 8, false><<<GB, dim3(16, 16)>>>(agg, W0, bi[0], fcw, fcb, h0);

    // ---- layer 1: 32 -> 64 ----
    gatherx<32, 1><<<GW, 256>>>(h0, g4 + N_EDGES, agg);
    gemm2<32, 64, 32, 4, 8, false><<<GB, dim3(16, 16)>>>(agg, W1, bi[1], fcw, fcb, h1);

    // ---- layer 2: 64 -> 64 (fused FC + log_softmax) ----
    gatherx<64, 2><<<GW, 256>>>(h1, g4 + 2 * (size_t)N_EDGES, agg);
    gemm2<64, 64, 32, 4, 8, true><<<GB, dim3(16, 16)>>>(agg, W2, bi[2], fcw, fcb, out);
}

// round 10
// speedup vs baseline: 1.6030x; 1.1809x over previous
#include <cuda_runtime.h>

#define N_NODES 163842
#define N_EDGES 983040
#define SCAN_B  1024
#define SCAN_NB ((N_NODES + SCAN_B - 1) / SCAN_B)   // 161

// ---------------- scratch (device globals; no allocation allowed) ----------------
__device__ float d_h0[(size_t)N_NODES * 64];
__device__ float d_h1[(size_t)N_NODES * 64];
__device__ float d_W[3][256 * 64];               // packed [4*Cin, Cout] per layer
__device__ float4 d_g4[3][N_EDGES];              // per-layer edge gaussians (CSR order)
__device__ int   d_csr_src[N_EDGES];
__device__ int   d_src[N_EDGES];
__device__ int   d_dst[N_EDGES];
__device__ int   d_cnt[N_NODES];
__device__ int   d_incl[N_NODES];
__device__ int   d_rowptr[N_NODES + 1];
__device__ int   d_cursor[N_NODES];
__device__ int   d_bsum[SCAN_NB];
__device__ int   d_is64;

// ---------------- edge index handling ----------------
__global__ void detect_kernel(const unsigned* ei) {
    if (threadIdx.x == 0) {
        int ok = 1;
        for (int i = 1; i < 64; i += 2)
            if (ei[i] != 0u) ok = 0;
        d_is64 = ok;
    }
}

__global__ void zero_cnt() {
    int i = blockIdx.x * blockDim.x + threadIdx.x;
    if (i < N_NODES) d_cnt[i] = 0;
}

__global__ void convert_hist(const void* eiv) {
    int e = blockIdx.x * blockDim.x + threadIdx.x;
    if (e >= N_EDGES) return;
    int s, d;
    if (d_is64) {
        const long long* ei = (const long long*)eiv;
        s = (int)ei[e]; d = (int)ei[N_EDGES + e];
    } else {
        const int* ei = (const int*)eiv;
        s = ei[e]; d = ei[N_EDGES + e];
    }
    d_src[e] = s;
    d_dst[e] = d;
    atomicAdd(&d_cnt[d], 1);
}

// ---------------- CSR build ----------------
__global__ void scan1() {
    __shared__ int s[2][SCAN_B];
    int t = threadIdx.x;
    int i = blockIdx.x * SCAN_B + t;
    int v = (i < N_NODES) ? d_cnt[i] : 0;
    s[0][t] = v;
    int cur = 0;
    for (int off = 1; off < SCAN_B; off <<= 1) {
        __syncthreads();
        int nv = s[cur][t] + (t >= off ? s[cur][t - off] : 0);
        s[cur ^ 1][t] = nv;
        cur ^= 1;
    }
    __syncthreads();
    if (i < N_NODES) d_incl[i] = s[cur][t];
    if (t == SCAN_B - 1) d_bsum[blockIdx.x] = s[cur][t];
}

__global__ void scan2() {
    __shared__ int s[2][256];
    int t = threadIdx.x;
    int v = (t < SCAN_NB) ? d_bsum[t] : 0;
    s[0][t] = v;
    int cur = 0;
    for (int off = 1; off < 256; off <<= 1) {
        __syncthreads();
        int nv = s[cur][t] + (t >= off ? s[cur][t - off] : 0);
        s[cur ^ 1][t] = nv;
        cur ^= 1;
    }
    __syncthreads();
    if (t < SCAN_NB) d_bsum[t] = s[cur][t] - v;        // exclusive
    if (t == 255) d_rowptr[N_NODES] = s[cur][t];
}

__global__ void scan3() {
    int i = blockIdx.x * blockDim.x + threadIdx.x;
    if (i >= N_NODES) return;
    int excl = d_incl[i] - d_cnt[i] + d_bsum[i / SCAN_B];
    d_rowptr[i] = excl;
    d_cursor[i] = excl;
}

// ---------------- fill CSR + all 3 layers' gaussians in one pass ------------------
__global__ void fill_gauss(const float* __restrict__ ea,
                           const float* __restrict__ mu0, const float* __restrict__ sg0,
                           const float* __restrict__ mu1, const float* __restrict__ sg1,
                           const float* __restrict__ mu2, const float* __restrict__ sg2) {
    int e = blockIdx.x * blockDim.x + threadIdx.x;
    if (e >= N_EDGES) return;
    int p = atomicAdd(&d_cursor[d_dst[e]], 1);
    d_csr_src[p] = d_src[e];
    float2 pc = ((const float2*)ea)[e];
    const float* mus[3] = {mu0, mu1, mu2};
    const float* sgs[3] = {sg0, sg1, sg2};
#pragma unroll
    for (int l = 0; l < 3; l++) {
        float g[3];
#pragma unroll
        for (int k = 0; k < 3; k++) {
            float dd0 = pc.x - mus[l][2 * k];
            float dd1 = pc.y - mus[l][2 * k + 1];
            float s0 = sgs[l][2 * k], s1 = sgs[l][2 * k + 1];
            float q = dd0 * dd0 / (1e-15f + s0 * s0) + dd1 * dd1 / (1e-15f + s1 * s1);
            g[k] = __expf(-0.5f * q);
        }
        d_g4[l][p] = make_float4(g[0], g[1], g[2], 0.f);
    }
}

// ---------------- pack weights: W[r, o], r<3Cin -> g (k=r/Cin,c=r%Cin), else root -
template <int CIN, int COUT>
__global__ void pack_w(const float* __restrict__ g,
                       const float* __restrict__ root,
                       float* __restrict__ W) {
    constexpr int K3 = 3 * CIN, K4 = 4 * CIN;
    int i = blockIdx.x * blockDim.x + threadIdx.x;
    if (i >= K4 * COUT) return;
    int r = i / COUT, col = i - r * COUT;
    float v;
    if (r < K3) {
        int k = r / CIN, c = r - k * CIN;
        v = g[c * (3 * COUT) + k * COUT + col];
    } else {
        v = root[(r - K3) * COUT + col];
    }
    W[i] = v;
}

// ---------------- fused layer: gather into smem, then GEMM + epilogue -------------
// BN=64 nodes/block, 256 threads. Phase 1: warp w gathers nodes [8w, 8w+8).
// Phase 2: block (16,16) GEMM out of smem xs with chunked weights.
template <int CIN, int COUT, int CC, int VW, bool FINAL>
__global__ void __launch_bounds__(256) layer_fused(const float* __restrict__ x,
                                                   const float4* __restrict__ g4,
                                                   const float* __restrict__ W,
                                                   const float* __restrict__ bias,
                                                   const float* __restrict__ fcw,
                                                   const float* __restrict__ fcb,
                                                   float* __restrict__ out) {
    constexpr int K4 = 4 * CIN;
    constexpr int XS = K4 + 4;                     // padded smem row
    constexpr int BN = 64;
    constexpr int TN = 4;                          // BN / 16
    constexpr int CPL = (CIN + 31) / 32;
    extern __shared__ __align__(16) float smem[];
    float* xs = smem;                              // [BN][XS]
    float* gs = smem + BN * XS;                    // [CC][COUT]

    const int tid = threadIdx.x;
    const int warp = tid >> 5, lane = tid & 31;
    const int n0 = blockIdx.x * BN;

    // ---- phase 1: gather ----
    for (int j = warp * 8; j < warp * 8 + 8; j++) {
        int n = n0 + j;
        if (n >= N_NODES) {                        // zero-pad oob rows
            for (int c = lane; c < XS; c += 32) xs[j * XS + c] = 0.f;
            continue;
        }
        int beg = d_rowptr[n], end = d_rowptr[n + 1];
        float acc[3][CPL];
#pragma unroll
        for (int k = 0; k < 3; k++)
#pragma unroll
            for (int r = 0; r < CPL; r++) acc[k][r] = 0.f;
        for (int i = beg; i < end; i++) {
            int s = d_csr_src[i];
            float4 gg = g4[i];
#pragma unroll
            for (int r = 0; r < CPL; r++) {
                int c = lane + 32 * r;
                float xv = (c < CIN) ? x[(size_t)s * CIN + c] : 0.f;
                acc[0][r] += gg.x * xv;
                acc[1][r] += gg.y * xv;
                acc[2][r] += gg.z * xv;
            }
        }
        float inv = 1.f / fmaxf((float)(end - beg), 1.f);
#pragma unroll
        for (int r = 0; r < CPL; r++) {
            int c = lane + 32 * r;
            if (c < CIN) {
#pragma unroll
                for (int k = 0; k < 3; k++)
                    xs[j * XS + k * CIN + c] = acc[k][r] * inv;
                xs[j * XS + 3 * CIN + c] = x[(size_t)n * CIN + c];
            }
        }
    }
    __syncthreads();

    // ---- phase 2: GEMM from smem ----
    const int tx = tid & 15, ty = tid >> 4;
    const int nb = ty * TN;
    float acc[TN][VW];
#pragma unroll
    for (int j = 0; j < TN; j++)
#pragma unroll
        for (int v = 0; v < VW; v++) acc[j][v] = 0.f;

    for (int c0 = 0; c0 < K4; c0 += CC) {
        for (int i = tid; i < CC * COUT / 4; i += 256)
            ((float4*)gs)[i] = ((const float4*)(W + c0 * COUT))[i];
        __syncthreads();
#pragma unroll
        for (int c4 = 0; c4 < CC; c4 += 4) {
            float4 xv[TN];
#pragma unroll
            for (int j = 0; j < TN; j++)
                xv[j] = *(const float4*)&xs[(nb + j) * XS + c0 + c4];
#pragma unroll
            for (int q = 0; q < 4; q++) {
                float wv[VW];
                if (VW == 4) {
                    float4 t = *(const float4*)&gs[(c4 + q) * COUT + tx * 4];
                    wv[0] = t.x; wv[1] = t.y; wv[2] = t.z; wv[3] = t.w;
                } else {
                    float2 t = *(const float2*)&gs[(c4 + q) * COUT + tx * 2];
                    wv[0] = t.x; wv[1] = t.y;
                }
#pragma unroll
                for (int j = 0; j < TN; j++) {
                    float xc = ((const float*)&xv[j])[q];
#pragma unroll
                    for (int v = 0; v < VW; v++) acc[j][v] += xc * wv[v];
                }
            }
        }
        __syncthreads();
    }

    // ---- epilogue ----
#pragma unroll
    for (int j = 0; j < TN; j++) {
        int n = n0 + nb + j;
        float hv[VW];
#pragma unroll
        for (int v = 0; v < VW; v++)
            hv[v] = fmaxf(acc[j][v] + bias[tx * VW + v], 0.f);
        if (!FINAL) {
            if (n < N_NODES) {
                if (VW == 4)
                    *(float4*)&out[(size_t)n * COUT + tx * 4] =
                        make_float4(hv[0], hv[1], hv[2], hv[3]);
                else
                    *(float2*)&out[(size_t)n * COUT + tx * 2] = make_float2(hv[0], hv[1]);
            }
        } else {
            float p0 = 0.f, p1 = 0.f;
#pragma unroll
            for (int v = 0; v < VW; v++) {
                int o = tx * VW + v;
                p0 += hv[v] * fcw[2 * o];
                p1 += hv[v] * fcw[2 * o + 1];
            }
#pragma unroll
            for (int off = 8; off > 0; off >>= 1) {   // reduce across 16 tx lanes
                p0 += __shfl_xor_sync(0xffffffffu, p0, off);
                p1 += __shfl_xor_sync(0xffffffffu, p1, off);
            }
            if (tx == 0 && n < N_NODES) {
                float l0 = p0 + fcb[0], l1 = p1 + fcb[1];
                float mx = fmaxf(l0, l1);
                float lse = mx + logf(expf(l0 - mx) + expf(l1 - mx));
                out[(size_t)n * 2]     = l0 - lse;
                out[(size_t)n * 2 + 1] = l1 - lse;
            }
        }
    }
}

// ---------------- launch ----------------------------------------------------------
extern "C" void kernel_launch(void* const* d_in, const int* in_sizes, int n_in,
                              void* d_out, int out_size) {
    const float* x   = (const float*)d_in[0];
    const void*  ei  = d_in[1];
    const float* ea  = (const float*)d_in[2];
    const float* g[3]  = {(const float*)d_in[3],  (const float*)d_in[8],  (const float*)d_in[13]};
    const float* mu[3] = {(const float*)d_in[4],  (const float*)d_in[9],  (const float*)d_in[14]};
    const float* sg[3] = {(const float*)d_in[5],  (const float*)d_in[10], (const float*)d_in[15]};
    const float* rt[3] = {(const float*)d_in[6],  (const float*)d_in[11], (const float*)d_in[16]};
    const float* bi[3] = {(const float*)d_in[7],  (const float*)d_in[12], (const float*)d_in[17]};
    const float* fcw = (const float*)d_in[18];
    const float* fcb = (const float*)d_in[19];
    float* out = (float*)d_out;

    float *h0, *h1, *W;
    float4* g4;
    cudaGetSymbolAddress((void**)&h0,  d_h0);
    cudaGetSymbolAddress((void**)&h1,  d_h1);
    cudaGetSymbolAddress((void**)&W,   d_W);
    cudaGetSymbolAddress((void**)&g4,  d_g4);
    float* W0 = W;
    float* W1 = W + 256 * 64;
    float* W2 = W + 2 * 256 * 64;

    // dynamic smem sizes: xs[64][4*Cin+4] + gs[CC][Cout]
    const int SM0 = (64 * 92  + 44 * 32) * 4;      // 29184 B
    const int SM1 = (64 * 132 + 32 * 64) * 4;      // 41984 B
    const int SM2 = (64 * 260 + 32 * 64) * 4;      // 74752 B
    cudaFuncSetAttribute(layer_fused<22, 32, 44, 2, false>,
                         cudaFuncAttributeMaxDynamicSharedMemorySize, SM0);
    cudaFuncSetAttribute(layer_fused<32, 64, 32, 4, false>,
                         cudaFuncAttributeMaxDynamicSharedMemorySize, SM1);
    cudaFuncSetAttribute(layer_fused<64, 64, 32, 4, true>,
                         cudaFuncAttributeMaxDynamicSharedMemorySize, SM2);

    const int EB = (N_EDGES + 255) / 256;
    const int NB = (N_NODES + 255) / 256;
    const int GB = (N_NODES + 63) / 64;            // fused-layer grids (BN=64)

    // ---- CSR build + weights pack (shared prep) ----
    detect_kernel<<<1, 32>>>((const unsigned*)ei);
    zero_cnt<<<NB, 256>>>();
    convert_hist<<<EB, 256>>>(ei);
    scan1<<<SCAN_NB, SCAN_B>>>();
    scan2<<<1, 256>>>();
    scan3<<<NB, 256>>>();
    fill_gauss<<<EB, 256>>>(ea, mu[0], sg[0], mu[1], sg[1], mu[2], sg[2]);
    pack_w<22, 32><<<(88 * 32 + 255) / 256, 256>>>(g[0], rt[0], W0);
    pack_w<32, 64><<<(128 * 64 + 255) / 256, 256>>>(g[1], rt[1], W1);
    pack_w<64, 64><<<(256 * 64 + 255) / 256, 256>>>(g[2], rt[2], W2);

    // ---- fused layers ----
    layer_fused<22, 32, 44, 2, false><<<GB, 256, SM0>>>(x,  g4,                          W0, bi[0], fcw, fcb, h0);
    layer_fused<32, 64, 32, 4, false><<<GB, 256, SM1>>>(h0, g4 + N_EDGES,                W1, bi[1], fcw, fcb, h1);
    layer_fused<64, 64, 32, 4, true ><<<GB, 256, SM2>>>(h1, g4 + 2 * (size_t)N_EDGES,    W2, bi[2], fcw, fcb, out);
}

// round 11
// speedup vs baseline: 1.6678x; 1.0404x over previous
#include <cuda_runtime.h>

#define N_NODES 163842
#define N_EDGES 983040
#define SCAN_B  1024
#define SCAN_NB ((N_NODES + SCAN_B - 1) / SCAN_B)   // 161

// ---------------- scratch (device globals; no allocation allowed) ----------------
__device__ float d_h0[(size_t)N_NODES * 64];
__device__ float d_h1[(size_t)N_NODES * 64];
__device__ float d_W[3][256 * 64];               // packed [4*Cin, Cout] per layer
__device__ float4 d_g4[3][N_EDGES];              // per-layer edge gaussians (CSR order)
__device__ int   d_csr_src[N_EDGES];
__device__ int   d_src[N_EDGES];
__device__ int   d_dst[N_EDGES];
__device__ int   d_cnt[N_NODES];
__device__ int   d_incl[N_NODES];
__device__ int   d_rowptr[N_NODES + 1];
__device__ int   d_cursor[N_NODES];
__device__ int   d_bsum[SCAN_NB];
__device__ int   d_is64;

// ---------------- packed f32x2 helpers ----------------
__device__ __forceinline__ unsigned long long pack2(float lo, float hi) {
    unsigned long long r;
    asm("mov.b64 %0, {%1, %2};" : "=l"(r) : "f"(lo), "f"(hi));
    return r;
}
__device__ __forceinline__ void unpack2(unsigned long long v, float& lo, float& hi) {
    asm("mov.b64 {%0, %1}, %2;" : "=f"(lo), "=f"(hi) : "l"(v));
}
__device__ __forceinline__ void ffma2(unsigned long long& d,
                                      unsigned long long a, unsigned long long b) {
    asm("fma.rn.f32x2 %0, %1, %2, %0;" : "+l"(d) : "l"(a), "l"(b));
}

// ---------------- edge index handling ----------------
__global__ void detect_kernel(const unsigned* ei) {
    if (threadIdx.x == 0) {
        int ok = 1;
        for (int i = 1; i < 64; i += 2)
            if (ei[i] != 0u) ok = 0;
        d_is64 = ok;
    }
}

__global__ void zero_cnt() {
    int i = blockIdx.x * blockDim.x + threadIdx.x;
    if (i < N_NODES) d_cnt[i] = 0;
}

__global__ void convert_hist(const void* eiv) {
    int e = blockIdx.x * blockDim.x + threadIdx.x;
    if (e >= N_EDGES) return;
    int s, d;
    if (d_is64) {
        const long long* ei = (const long long*)eiv;
        s = (int)ei[e]; d = (int)ei[N_EDGES + e];
    } else {
        const int* ei = (const int*)eiv;
        s = ei[e]; d = ei[N_EDGES + e];
    }
    d_src[e] = s;
    d_dst[e] = d;
    atomicAdd(&d_cnt[d], 1);
}

// ---------------- CSR build ----------------
__global__ void scan1() {
    __shared__ int s[2][SCAN_B];
    int t = threadIdx.x;
    int i = blockIdx.x * SCAN_B + t;
    int v = (i < N_NODES) ? d_cnt[i] : 0;
    s[0][t] = v;
    int cur = 0;
    for (int off = 1; off < SCAN_B; off <<= 1) {
        __syncthreads();
        int nv = s[cur][t] + (t >= off ? s[cur][t - off] : 0);
        s[cur ^ 1][t] = nv;
        cur ^= 1;
    }
    __syncthreads();
    if (i < N_NODES) d_incl[i] = s[cur][t];
    if (t == SCAN_B - 1) d_bsum[blockIdx.x] = s[cur][t];
}

__global__ void scan2() {
    __shared__ int s[2][256];
    int t = threadIdx.x;
    int v = (t < SCAN_NB) ? d_bsum[t] : 0;
    s[0][t] = v;
    int cur = 0;
    for (int off = 1; off < 256; off <<= 1) {
        __syncthreads();
        int nv = s[cur][t] + (t >= off ? s[cur][t - off] : 0);
        s[cur ^ 1][t] = nv;
        cur ^= 1;
    }
    __syncthreads();
    if (t < SCAN_NB) d_bsum[t] = s[cur][t] - v;        // exclusive
    if (t == 255) d_rowptr[N_NODES] = s[cur][t];
}

__global__ void scan3() {
    int i = blockIdx.x * blockDim.x + threadIdx.x;
    if (i >= N_NODES) return;
    int excl = d_incl[i] - d_cnt[i] + d_bsum[i / SCAN_B];
    d_rowptr[i] = excl;
    d_cursor[i] = excl;
}

// ---------------- fill CSR + all 3 layers' gaussians in one pass ------------------
__global__ void fill_gauss(const float* __restrict__ ea,
                           const float* __restrict__ mu0, const float* __restrict__ sg0,
                           const float* __restrict__ mu1, const float* __restrict__ sg1,
                           const float* __restrict__ mu2, const float* __restrict__ sg2) {
    int e = blockIdx.x * blockDim.x + threadIdx.x;
    if (e >= N_EDGES) return;
    int p = atomicAdd(&d_cursor[d_dst[e]], 1);
    d_csr_src[p] = d_src[e];
    float2 pc = ((const float2*)ea)[e];
    const float* mus[3] = {mu0, mu1, mu2};
    const float* sgs[3] = {sg0, sg1, sg2};
#pragma unroll
    for (int l = 0; l < 3; l++) {
        float g[3];
#pragma unroll
        for (int k = 0; k < 3; k++) {
            float dd0 = pc.x - mus[l][2 * k];
            float dd1 = pc.y - mus[l][2 * k + 1];
            float s0 = sgs[l][2 * k], s1 = sgs[l][2 * k + 1];
            float q = dd0 * dd0 / (1e-15f + s0 * s0) + dd1 * dd1 / (1e-15f + s1 * s1);
            g[k] = __expf(-0.5f * q);
        }
        d_g4[l][p] = make_float4(g[0], g[1], g[2], 0.f);
    }
}

// ---------------- pack weights: W[r, o], r<3Cin -> g (k=r/Cin,c=r%Cin), else root -
template <int CIN, int COUT>
__global__ void pack_w(const float* __restrict__ g,
                       const float* __restrict__ root,
                       float* __restrict__ W) {
    constexpr int K3 = 3 * CIN, K4 = 4 * CIN;
    int i = blockIdx.x * blockDim.x + threadIdx.x;
    if (i >= K4 * COUT) return;
    int r = i / COUT, col = i - r * COUT;
    float v;
    if (r < K3) {
        int k = r / CIN, c = r - k * CIN;
        v = g[c * (3 * COUT) + k * COUT + col];
    } else {
        v = root[(r - K3) * COUT + col];
    }
    W[i] = v;
}

// ---------------- fused layer: gather into smem, then f32x2 GEMM + epilogue -------
// BN=64 nodes/block, 256 threads. Phase 1: warp w gathers nodes [8w, 8w+8).
// Phase 2: block (16,16) GEMM out of smem xs with chunked weights, FFMA2 inner loop.
template <int CIN, int COUT, int CC, int VW, bool FINAL>
__global__ void __launch_bounds__(256) layer_fused(const float* __restrict__ x,
                                                   const float4* __restrict__ g4,
                                                   const float* __restrict__ W,
                                                   const float* __restrict__ bias,
                                                   const float* __restrict__ fcw,
                                                   const float* __restrict__ fcb,
                                                   float* __restrict__ out) {
    constexpr int K4 = 4 * CIN;
    constexpr int XS = K4 + 4;                     // padded smem row
    constexpr int BN = 64;
    constexpr int TN = 4;                          // BN / 16
    constexpr int VP = VW / 2;                     // accumulator pairs per node
    constexpr int CPL = (CIN + 31) / 32;
    extern __shared__ __align__(16) float smem[];
    float* xs = smem;                              // [BN][XS]
    float* gs = smem + BN * XS;                    // [CC][COUT]

    const int tid = threadIdx.x;
    const int warp = tid >> 5, lane = tid & 31;
    const int n0 = blockIdx.x * BN;

    // ---- phase 1: gather ----
    for (int j = warp * 8; j < warp * 8 + 8; j++) {
        int n = n0 + j;
        if (n >= N_NODES) {                        // zero-pad oob rows
            for (int c = lane; c < XS; c += 32) xs[j * XS + c] = 0.f;
            continue;
        }
        int beg = d_rowptr[n], end = d_rowptr[n + 1];
        float acc[3][CPL];
#pragma unroll
        for (int k = 0; k < 3; k++)
#pragma unroll
            for (int r = 0; r < CPL; r++) acc[k][r] = 0.f;
        for (int i = beg; i < end; i++) {
            int s = d_csr_src[i];
            float4 gg = g4[i];
#pragma unroll
            for (int r = 0; r < CPL; r++) {
                int c = lane + 32 * r;
                float xv = (c < CIN) ? x[(size_t)s * CIN + c] : 0.f;
                acc[0][r] += gg.x * xv;
                acc[1][r] += gg.y * xv;
                acc[2][r] += gg.z * xv;
            }
        }
        float inv = 1.f / fmaxf((float)(end - beg), 1.f);
#pragma unroll
        for (int r = 0; r < CPL; r++) {
            int c = lane + 32 * r;
            if (c < CIN) {
#pragma unroll
                for (int k = 0; k < 3; k++)
                    xs[j * XS + k * CIN + c] = acc[k][r] * inv;
                xs[j * XS + 3 * CIN + c] = x[(size_t)n * CIN + c];
            }
        }
    }
    __syncthreads();

    // ---- phase 2: GEMM from smem (packed f32x2 accumulation) ----
    const int tx = tid & 15, ty = tid >> 4;
    const int nb = ty * TN;
    unsigned long long accp[TN][VP];               // pairs of adjacent outputs
#pragma unroll
    for (int j = 0; j < TN; j++)
#pragma unroll
        for (int v = 0; v < VP; v++) accp[j][v] = 0ull;

    for (int c0 = 0; c0 < K4; c0 += CC) {
        for (int i = tid; i < CC * COUT / 4; i += 256)
            ((float4*)gs)[i] = ((const float4*)(W + c0 * COUT))[i];
        __syncthreads();
#pragma unroll
        for (int c4 = 0; c4 < CC; c4 += 4) {
            float4 xv[TN];
#pragma unroll
            for (int j = 0; j < TN; j++)
                xv[j] = *(const float4*)&xs[(nb + j) * XS + c0 + c4];
#pragma unroll
            for (int q = 0; q < 4; q++) {
                unsigned long long wp[VP];
                if (VW == 4) {
                    float4 t = *(const float4*)&gs[(c4 + q) * COUT + tx * 4];
                    wp[0] = pack2(t.x, t.y);
                    wp[VP - 1] = pack2(t.z, t.w);   // VP==2
                } else {
                    float2 t = *(const float2*)&gs[(c4 + q) * COUT + tx * 2];
                    wp[0] = pack2(t.x, t.y);
                }
#pragma unroll
                for (int j = 0; j < TN; j++) {
                    float xc = ((const float*)&xv[j])[q];
                    unsigned long long xb = pack2(xc, xc);
#pragma unroll
                    for (int v = 0; v < VP; v++) ffma2(accp[j][v], wp[v], xb);
                }
            }
        }
        __syncthreads();
    }

    // ---- epilogue ----
#pragma unroll
    for (int j = 0; j < TN; j++) {
        int n = n0 + nb + j;
        float hv[VW];
#pragma unroll
        for (int v = 0; v < VP; v++) {
            float lo, hi;
            unpack2(accp[j][v], lo, hi);
            hv[2 * v]     = fmaxf(lo + bias[tx * VW + 2 * v], 0.f);
            hv[2 * v + 1] = fmaxf(hi + bias[tx * VW + 2 * v + 1], 0.f);
        }
        if (!FINAL) {
            if (n < N_NODES) {
                if (VW == 4)
                    *(float4*)&out[(size_t)n * COUT + tx * 4] =
                        make_float4(hv[0], hv[1], hv[2], hv[3]);
                else
                    *(float2*)&out[(size_t)n * COUT + tx * 2] = make_float2(hv[0], hv[1]);
            }
        } else {
            float p0 = 0.f, p1 = 0.f;
#pragma unroll
            for (int v = 0; v < VW; v++) {
                int o = tx * VW + v;
                p0 += hv[v] * fcw[2 * o];
                p1 += hv[v] * fcw[2 * o + 1];
            }
#pragma unroll
            for (int off = 8; off > 0; off >>= 1) {   // reduce across 16 tx lanes
                p0 += __shfl_xor_sync(0xffffffffu, p0, off);
                p1 += __shfl_xor_sync(0xffffffffu, p1, off);
            }
            if (tx == 0 && n < N_NODES) {
                float l0 = p0 + fcb[0], l1 = p1 + fcb[1];
                float mx = fmaxf(l0, l1);
                float lse = mx + logf(expf(l0 - mx) + expf(l1 - mx));
                out[(size_t)n * 2]     = l0 - lse;
                out[(size_t)n * 2 + 1] = l1 - lse;
            }
        }
    }
}

// ---------------- launch ----------------------------------------------------------
extern "C" void kernel_launch(void* const* d_in, const int* in_sizes, int n_in,
                              void* d_out, int out_size) {
    const float* x   = (const float*)d_in[0];
    const void*  ei  = d_in[1];
    const float* ea  = (const float*)d_in[2];
    const float* g[3]  = {(const float*)d_in[3],  (const float*)d_in[8],  (const float*)d_in[13]};
    const float* mu[3] = {(const float*)d_in[4],  (const float*)d_in[9],  (const float*)d_in[14]};
    const float* sg[3] = {(const float*)d_in[5],  (const float*)d_in[10], (const float*)d_in[15]};
    const float* rt[3] = {(const float*)d_in[6],  (const float*)d_in[11], (const float*)d_in[16]};
    const float* bi[3] = {(const float*)d_in[7],  (const float*)d_in[12], (const float*)d_in[17]};
    const float* fcw = (const float*)d_in[18];
    const float* fcb = (const float*)d_in[19];
    float* out = (float*)d_out;

    float *h0, *h1, *W;
    float4* g4;
    cudaGetSymbolAddress((void**)&h0,  d_h0);
    cudaGetSymbolAddress((void**)&h1,  d_h1);
    cudaGetSymbolAddress((void**)&W,   d_W);
    cudaGetSymbolAddress((void**)&g4,  d_g4);
    float* W0 = W;
    float* W1 = W + 256 * 64;
    float* W2 = W + 2 * 256 * 64;

    // dynamic smem sizes: xs[64][4*Cin+4] + gs[CC][Cout]
    const int SM0 = (64 * 92  + 44 * 32) * 4;      // 29184 B
    const int SM1 = (64 * 132 + 32 * 64) * 4;      // 41984 B
    const int SM2 = (64 * 260 + 32 * 64) * 4;      // 74752 B
    cudaFuncSetAttribute(layer_fused<22, 32, 44, 2, false>,
                         cudaFuncAttributeMaxDynamicSharedMemorySize, SM0);
    cudaFuncSetAttribute(layer_fused<32, 64, 32, 4, false>,
                         cudaFuncAttributeMaxDynamicSharedMemorySize, SM1);
    cudaFuncSetAttribute(layer_fused<64, 64, 32, 4, true>,
                         cudaFuncAttributeMaxDynamicSharedMemorySize, SM2);

    const int EB = (N_EDGES + 255) / 256;
    const int NB = (N_NODES + 255) / 256;
    const int GB = (N_NODES + 63) / 64;            // fused-layer grids (BN=64)

    // ---- CSR build + weights pack (shared prep) ----
    detect_kernel<<<1, 32>>>((const unsigned*)ei);
    zero_cnt<<<NB, 256>>>();
    convert_hist<<<EB, 256>>>(ei);
    scan1<<<SCAN_NB, SCAN_B>>>();
    scan2<<<1, 256>>>();
    scan3<<<NB, 256>>>();
    fill_gauss<<<EB, 256>>>(ea, mu[0], sg[0], mu[1], sg[1], mu[2], sg[2]);
    pack_w<22, 32><<<(88 * 32 + 255) / 256, 256>>>(g[0], rt[0], W0);
    pack_w<32, 64><<<(128 * 64 + 255) / 256, 256>>>(g[1], rt[1], W1);
    pack_w<64, 64><<<(256 * 64 + 255) / 256, 256>>>(g[2], rt[2], W2);

    // ---- fused layers ----
    layer_fused<22, 32, 44, 2, false><<<GB, 256, SM0>>>(x,  g4,                          W0, bi[0], fcw, fcb, h0);
    layer_fused<32, 64, 32, 4, false><<<GB, 256, SM1>>>(h0, g4 + N_EDGES,                W1, bi[1], fcw, fcb, h1);
    layer_fused<64, 64, 32, 4, true ><<<GB, 256, SM2>>>(h1, g4 + 2 * (size_t)N_EDGES,    W2, bi[2], fcw, fcb, out);
}